// round 2
// baseline (speedup 1.0000x reference)
#include <cuda_runtime.h>
#include <math.h>

#define BB 16
#define SS 1024
#define NB 64
#define NSTEP 16   // 1024/64

// ---- static device scratch (allocation-free) ----
static __device__ float g_M [(size_t)BB * SS * SS];  // 64 MB: padded minors -> inverses
static __device__ float g_MT[(size_t)BB * SS * SS];  // 64 MB: transposed inverses
static __device__ double g_r[BB * SS];               // fp64 row sums
static __device__ unsigned long long g_maxkey;       // (sortable-key<<32)|argmax; atomicMax idempotent

__device__ __forceinline__ unsigned int enc_f(float v) {
    unsigned int u = __float_as_uint(v);
    return (u & 0x80000000u) ? ~u : (u | 0x80000000u);
}
__device__ __forceinline__ float dec_f(unsigned int k) {
    unsigned int u = (k & 0x80000000u) ? (k ^ 0x80000000u) : ~k;
    return __uint_as_float(u);
}
__device__ __forceinline__ float get_m() { return dec_f((unsigned int)(g_maxkey >> 32)); }

// ---------------- global max + argmax ----------------
__global__ void k_max(const float* __restrict__ s) {
    __shared__ unsigned long long sm[256];
    unsigned long long best = 0ULL;
    const size_t total = (size_t)BB * SS * SS;
    for (size_t i = (size_t)blockIdx.x * blockDim.x + threadIdx.x; i < total;
         i += (size_t)gridDim.x * blockDim.x) {
        unsigned long long c = ((unsigned long long)enc_f(s[i]) << 32) | (unsigned int)i;
        if (c > best) best = c;
    }
    sm[threadIdx.x] = best;
    __syncthreads();
    for (int o = 128; o > 0; o >>= 1) {
        if (threadIdx.x < o && sm[threadIdx.x + o] > sm[threadIdx.x]) sm[threadIdx.x] = sm[threadIdx.x + o];
        __syncthreads();
    }
    if (threadIdx.x == 0) atomicMax(&g_maxkey, sm[0]);
}

// ---------------- fp64 row sums of A = exp(s - m) ----------------
__global__ void k_rowsum(const float* __restrict__ s) {
    __shared__ double sd[256];
    const int row = blockIdx.x;                    // 0 .. BB*SS-1
    const float m = get_m();
    const float* p = s + ((size_t)row << 10);
    double acc = 0.0;
    for (int j = threadIdx.x; j < SS; j += 256) acc += (double)expf(p[j] - m);
    sd[threadIdx.x] = acc;
    __syncthreads();
    for (int o = 128; o > 0; o >>= 1) {
        if (threadIdx.x < o) sd[threadIdx.x] += sd[threadIdx.x + o];
        __syncthreads();
    }
    if (threadIdx.x == 0) g_r[row] = sd[0];
}

// ---------------- build padded M (identity row/col at index 1023) ----------------
__global__ void k_build(const float* __restrict__ s) {
    const float m = get_m();
    const size_t t = (size_t)blockIdx.x * 256 + threadIdx.x;   // exactly 16M threads
    const int q = (int)(t & 1023);
    const int p = (int)((t >> 10) & 1023);
    const int b = (int)(t >> 20);
    float v;
    if (p < 1023 && q < 1023) {
        float a = expf(s[((size_t)b << 20) + ((size_t)(p + 1) << 10) + (q + 1)] - m);
        v = -a;
        if (p == q) v = (float)(g_r[b * SS + p + 1] - (double)a);
    } else {
        v = (p == q) ? 1.0f : 0.0f;
    }
    g_M[t] = v;
}

// ---------------- invert 64x64 pivot block in place (Gauss-Jordan sweep) ----------------
__global__ void __launch_bounds__(256) k_inv(int kstep) {
    __shared__ float a[NB][NB + 1];
    __shared__ float rowp[NB], colp[NB];
    const int b = blockIdx.x, tid = threadIdx.x;
    float* blk = g_M + ((size_t)b << 20) + (((size_t)kstep * NB) << 10) + (size_t)kstep * NB;
    for (int f = tid; f < NB * NB; f += 256)
        a[f >> 6][f & 63] = blk[((size_t)(f >> 6) << 10) + (f & 63)];
    __syncthreads();
    for (int p = 0; p < NB; p++) {
        if (tid < NB) { rowp[tid] = a[p][tid]; colp[tid] = a[tid][p]; }
        __syncthreads();
        const float pinv = 1.0f / rowp[p];
        for (int f = tid; f < NB * NB; f += 256) {
            const int i = f >> 6, j = f & 63;
            float v;
            if (i == p)      v = (j == p) ? pinv : rowp[j] * pinv;
            else if (j == p) v = -colp[i] * pinv;
            else             v = a[i][j] - colp[i] * rowp[j] * pinv;
            a[i][j] = v;
        }
        __syncthreads();
    }
    for (int f = tid; f < NB * NB; f += 256)
        blk[((size_t)(f >> 6) << 10) + (f & 63)] = a[f >> 6][f & 63];
}

// ---------------- 64x64x64 block GEMM for the Jordan sweep ----------------
// mode 0:  C(k,jb)  =  P(k,k) @ A(k,jb)            (run 1st)
// mode 2:  C(ib,jb) -= A(ib,k)_old @ A(k,jb)_new   (run 2nd)
// mode 1:  C(ib,k)  = -A(ib,k)_old @ P(k,k)        (run last)
__global__ void __launch_bounds__(256) k_gemm(int kstep, int mode) {
    __shared__ float AsT[NB * 68];   // AsT[k][i]
    __shared__ float Bs [NB * 68];   // Bs [k][j]
    int b, ib, jb;
    if (mode == 2) {
        b  = blockIdx.z;
        ib = blockIdx.y + (blockIdx.y >= kstep);
        jb = blockIdx.x + (blockIdx.x >= kstep);
    } else {
        b  = blockIdx.y;
        const int o = blockIdx.x + ((int)blockIdx.x >= kstep);
        ib = (mode == 0) ? kstep : o;
        jb = (mode == 0) ? o : kstep;
    }
    const int arow = (mode == 0) ? kstep : ib;   // A-operand block = (arow, kstep)
    const int bcol = (mode == 1) ? kstep : jb;   // B-operand block = (kstep, bcol)

    const size_t base = (size_t)b << 20;
    const float* Ag = g_M + base + (((size_t)arow  * NB) << 10) + (size_t)kstep * NB;
    const float* Bg = g_M + base + (((size_t)kstep * NB) << 10) + (size_t)bcol  * NB;
    float*       Cg = g_M + base + (((size_t)ib    * NB) << 10) + (size_t)jb    * NB;

    const int tid = threadIdx.x;
    #pragma unroll
    for (int f = tid; f < 1024; f += 256) {       // 1024 float4 per tile
        const int r  = f >> 4;                    // 0..63
        const int c4 = (f & 15) << 2;             // 0..60
        float4 av = *(const float4*)(Ag + ((size_t)r << 10) + c4);
        AsT[(c4 + 0) * 68 + r] = av.x;
        AsT[(c4 + 1) * 68 + r] = av.y;
        AsT[(c4 + 2) * 68 + r] = av.z;
        AsT[(c4 + 3) * 68 + r] = av.w;
        *(float4*)(Bs + r * 68 + c4) = *(const float4*)(Bg + ((size_t)r << 10) + c4);
    }
    __syncthreads();

    const int j0 = (tid & 15) * 4;
    const int i0 = (tid >> 4) * 4;
    float acc[4][4] = {};
    #pragma unroll 8
    for (int kk = 0; kk < NB; kk++) {
        const float4 a = *(const float4*)(AsT + kk * 68 + i0);
        const float4 v = *(const float4*)(Bs  + kk * 68 + j0);
        acc[0][0] += a.x * v.x; acc[0][1] += a.x * v.y; acc[0][2] += a.x * v.z; acc[0][3] += a.x * v.w;
        acc[1][0] += a.y * v.x; acc[1][1] += a.y * v.y; acc[1][2] += a.y * v.z; acc[1][3] += a.y * v.w;
        acc[2][0] += a.z * v.x; acc[2][1] += a.z * v.y; acc[2][2] += a.z * v.z; acc[2][3] += a.z * v.w;
        acc[3][0] += a.w * v.x; acc[3][1] += a.w * v.y; acc[3][2] += a.w * v.z; acc[3][3] += a.w * v.w;
    }

    if (mode == 2) {
        #pragma unroll
        for (int r = 0; r < 4; r++) {
            float4 c = *(float4*)(Cg + ((size_t)(i0 + r) << 10) + j0);
            c.x -= acc[r][0]; c.y -= acc[r][1]; c.z -= acc[r][2]; c.w -= acc[r][3];
            *(float4*)(Cg + ((size_t)(i0 + r) << 10) + j0) = c;
        }
    } else {
        const float sgn = (mode == 1) ? -1.0f : 1.0f;
        #pragma unroll
        for (int r = 0; r < 4; r++) {
            float4 c;
            c.x = sgn * acc[r][0]; c.y = sgn * acc[r][1];
            c.z = sgn * acc[r][2]; c.w = sgn * acc[r][3];
            *(float4*)(Cg + ((size_t)(i0 + r) << 10) + j0) = c;
        }
    }
}

// ---------------- tiled transpose: g_MT[b] = g_M[b]^T ----------------
__global__ void k_transpose() {
    __shared__ float tile[32][33];
    const int b = blockIdx.z;
    const int x0 = blockIdx.x * 32, y0 = blockIdx.y * 32;
    const size_t base = (size_t)b << 20;
    for (int r = threadIdx.y; r < 32; r += 8)
        tile[r][threadIdx.x] = g_M[base + ((size_t)(y0 + r) << 10) + x0 + threadIdx.x];
    __syncthreads();
    for (int r = threadIdx.y; r < 32; r += 8)
        g_MT[base + ((size_t)(x0 + r) << 10) + y0 + threadIdx.x] = tile[threadIdx.x][r];
}

// ---------------- assemble probs ----------------
__global__ void k_out(const float* __restrict__ s, float* __restrict__ out) {
    const size_t t = (size_t)blockIdx.x * 256 + threadIdx.x;   // exactly 16M threads
    const int q = (int)(t & 1023);
    const int p = (int)((t >> 10) & 1023);
    const int b = (int)(t >> 20);
    const float m = get_m();
    const unsigned int amax = (unsigned int)(g_maxkey & 0xffffffffu);
    float v = 0.0f;
    if (p >= 1) {
        const float* MT = g_MT + ((size_t)b << 20) + ((size_t)(p - 1) << 10);
        const float dg  = MT[p - 1];                     // Minv[p-1][p-1]
        const float sub = (q >= 1) ? MT[q - 1] : 0.0f;   // Minv[q-1][p-1]
        v = expf(s[t] - m) * (dg - sub);
    }
    if ((unsigned int)t == amax) v += 16.0f;             // grad through the global max
    out[t] = v;
}

extern "C" void kernel_launch(void* const* d_in, const int* in_sizes, int n_in,
                              void* d_out, int out_size) {
    (void)in_sizes; (void)n_in; (void)out_size;
    const float* s = (const float*)d_in[0];
    float* out = (float*)d_out;

    k_max<<<2048, 256>>>(s);
    k_rowsum<<<BB * SS, 256>>>(s);
    k_build<<<65536, 256>>>(s);

    for (int k = 0; k < NSTEP; k++) {
        k_inv<<<BB, 256>>>(k);
        k_gemm<<<dim3(NSTEP - 1, BB), 256>>>(k, 0);                 // row panel
        k_gemm<<<dim3(NSTEP - 1, NSTEP - 1, BB), 256>>>(k, 2);      // trailing update
        k_gemm<<<dim3(NSTEP - 1, BB), 256>>>(k, 1);                 // col panel
    }

    k_transpose<<<dim3(32, 32, BB), dim3(32, 8)>>>();
    k_out<<<65536, 256>>>(s, out);
}

// round 3
// speedup vs baseline: 1.3827x; 1.3827x over previous
#include <cuda_runtime.h>
#include <math.h>

#define BB 16
#define SS 1024
#define NB 64
#define NSTEP 16   // 1024/64

// ---- static device scratch (allocation-free) ----
static __device__ float g_M [(size_t)BB * SS * SS];   // 64 MB: padded minors -> inverses
static __device__ float g_MT[(size_t)BB * SS * SS];   // 64 MB: transposed inverses
static __device__ float g_S [(size_t)BB * NB * SS];   // 4 MB: stashed old row stripe + P^-1 slot
static __device__ double g_r[BB * SS];                // fp64 row sums
static __device__ unsigned long long g_maxkey;        // (sortable-key<<32)|argmax; atomicMax idempotent

__device__ __forceinline__ unsigned int enc_f(float v) {
    unsigned int u = __float_as_uint(v);
    return (u & 0x80000000u) ? ~u : (u | 0x80000000u);
}
__device__ __forceinline__ float dec_f(unsigned int k) {
    unsigned int u = (k & 0x80000000u) ? (k ^ 0x80000000u) : ~k;
    return __uint_as_float(u);
}
__device__ __forceinline__ float get_m() { return dec_f((unsigned int)(g_maxkey >> 32)); }

// ---------------- global max + argmax ----------------
__global__ void k_max(const float* __restrict__ s) {
    __shared__ unsigned long long sm[256];
    unsigned long long best = 0ULL;
    const size_t total = (size_t)BB * SS * SS;
    for (size_t i = (size_t)blockIdx.x * blockDim.x + threadIdx.x; i < total;
         i += (size_t)gridDim.x * blockDim.x) {
        unsigned long long c = ((unsigned long long)enc_f(s[i]) << 32) | (unsigned int)i;
        if (c > best) best = c;
    }
    sm[threadIdx.x] = best;
    __syncthreads();
    for (int o = 128; o > 0; o >>= 1) {
        if (threadIdx.x < o && sm[threadIdx.x + o] > sm[threadIdx.x]) sm[threadIdx.x] = sm[threadIdx.x + o];
        __syncthreads();
    }
    if (threadIdx.x == 0) atomicMax(&g_maxkey, sm[0]);
}

// ---------------- fp64 row sums of A = exp(s - m) ----------------
__global__ void k_rowsum(const float* __restrict__ s) {
    __shared__ double sd[256];
    const int row = blockIdx.x;                    // 0 .. BB*SS-1
    const float m = get_m();
    const float* p = s + ((size_t)row << 10);
    double acc = 0.0;
    for (int j = threadIdx.x; j < SS; j += 256) acc += (double)expf(p[j] - m);
    sd[threadIdx.x] = acc;
    __syncthreads();
    for (int o = 128; o > 0; o >>= 1) {
        if (threadIdx.x < o) sd[threadIdx.x] += sd[threadIdx.x + o];
        __syncthreads();
    }
    if (threadIdx.x == 0) g_r[row] = sd[0];
}

// ---------------- build padded M (identity row/col at index 1023) ----------------
__global__ void k_build(const float* __restrict__ s) {
    const float m = get_m();
    const size_t t = (size_t)blockIdx.x * 256 + threadIdx.x;   // exactly 16M threads
    const int q = (int)(t & 1023);
    const int p = (int)((t >> 10) & 1023);
    const int b = (int)(t >> 20);
    float v;
    if (p < 1023 && q < 1023) {
        float a = expf(s[((size_t)b << 20) + ((size_t)(p + 1) << 10) + (q + 1)] - m);
        v = -a;
        if (p == q) v = (float)(g_r[b * SS + p + 1] - (double)a);
    } else {
        v = (p == q) ? 1.0f : 0.0f;
    }
    g_M[t] = v;
}

// =====================================================================
// Fused panel kernel, one launch per GJ step.
//   grid (31, BB):
//     x in [0,15)  : row panel  C(k,jb) = P^-1 @ Aold(k,jb); stash Aold(k,jb) -> g_S
//     x in [15,30) : col panel  C(ib,k) = -Aold(ib,k) @ P^-1
//     x == 30      : write P^-1 into g_S stripe slot k (NOT g_M: avoids an
//                    intra-kernel race with CTAs still reading the old pivot)
// Every CTA redundantly inverts the 64x64 pivot in registers (8 warps x 8
// rows x 2 cols/lane), 1 __syncthreads per pivot step, pivot column via shfl.
// =====================================================================
__global__ void __launch_bounds__(256) k_panel(int k) {
    __shared__ float sOp [NB * 68];     // other operand (AsT for col panel, Bs for row panel)
    __shared__ float sPiv[NB * 68];     // P^-1 deposit (transposed for row panel, plain for col)
    __shared__ float rowbuf[2][NB];

    const int b = blockIdx.y;
    const int x = blockIdx.x;
    const int tid = threadIdx.x;
    const int w = tid >> 5, l = tid & 31;
    const size_t base = (size_t)b << 20;
    const int role = (x < 15) ? 0 : (x < 30 ? 1 : 2);

    // ---- load pivot block into registers: pr[r][c] = P[w*8+r][l+32c] ----
    float pr[8][2];
    const float* Pg = g_M + base + (((size_t)k * NB) << 10) + (size_t)k * NB;
    #pragma unroll
    for (int r = 0; r < 8; r++) {
        pr[r][0] = Pg[((size_t)(w * 8 + r) << 10) + l];
        pr[r][1] = Pg[((size_t)(w * 8 + r) << 10) + l + 32];
    }

    // ---- load the other operand tile into shared ----
    int ib = k, jb = k;
    if (role == 0) {
        jb = x + (x >= k);
        const float* Bg = g_M + base + (((size_t)k * NB) << 10) + (size_t)jb * NB;
        float* Sg = g_S + ((size_t)b << 16) + (size_t)jb * NB;
        #pragma unroll
        for (int f = tid; f < 1024; f += 256) {
            const int r = f >> 4, c4 = (f & 15) << 2;
            float4 v = *(const float4*)(Bg + ((size_t)r << 10) + c4);
            *(float4*)(sOp + r * 68 + c4) = v;                 // Bs plain
            *(float4*)(Sg + (size_t)r * SS + c4) = v;          // stash old row tile
        }
    } else if (role == 1) {
        ib = (x - 15) + ((x - 15) >= k);
        const float* Ag = g_M + base + (((size_t)ib * NB) << 10) + (size_t)k * NB;
        #pragma unroll
        for (int f = tid; f < 1024; f += 256) {
            const int r = f >> 4, c4 = (f & 15) << 2;
            float4 v = *(const float4*)(Ag + ((size_t)r << 10) + c4);
            sOp[(c4 + 0) * 68 + r] = v.x;                      // AsT[k][i]
            sOp[(c4 + 1) * 68 + r] = v.y;
            sOp[(c4 + 2) * 68 + r] = v.z;
            sOp[(c4 + 3) * 68 + r] = v.w;
        }
    }

    // ---- register Gauss-Jordan inversion of the pivot ----
    for (int pw = 0; pw < 8; pw++) {               // keep rolled: small I$ footprint
        #pragma unroll
        for (int rp = 0; rp < 8; rp++) {
            const int p = pw * 8 + rp;
            float* buf = rowbuf[rp & 1];
            if (w == pw) { buf[l] = pr[rp][0]; buf[l + 32] = pr[rp][1]; }
            __syncthreads();
            const float r0 = buf[l], r1 = buf[l + 32];
            const float pinv = 1.0f / buf[p];
            const bool hi = (p >= 32);
            const int pl = p & 31;
            #pragma unroll
            for (int r = 0; r < 8; r++) {
                const float src = hi ? pr[r][1] : pr[r][0];
                const float colv = __shfl_sync(0xffffffffu, src, pl);
                if (r == rp && w == pw) {
                    pr[r][0] = r0 * pinv;
                    pr[r][1] = r1 * pinv;
                    if (l == pl) { if (hi) pr[r][1] = pinv; else pr[r][0] = pinv; }
                } else {
                    const float sc = colv * pinv;
                    pr[r][0] -= sc * r0;
                    pr[r][1] -= sc * r1;
                    if (l == pl) { if (hi) pr[r][1] = -sc; else pr[r][0] = -sc; }
                }
            }
        }
    }

    // ---- deposit P^-1 / store ----
    if (role == 2) {
        // write P^-1 to the unused stripe slot k of g_S (copied to g_M by k_trail)
        float* Sg = g_S + ((size_t)b << 16) + (size_t)k * NB;
        #pragma unroll
        for (int r = 0; r < 8; r++) {
            Sg[(size_t)(w * 8 + r) * SS + l]      = pr[r][0];
            Sg[(size_t)(w * 8 + r) * SS + l + 32] = pr[r][1];
        }
        return;
    }
    if (role == 0) {       // transposed: sPiv[kk][i] = Pinv[i][kk]
        #pragma unroll
        for (int r = 0; r < 8; r++) {
            sPiv[(l)      * 68 + (w * 8 + r)] = pr[r][0];
            sPiv[(l + 32) * 68 + (w * 8 + r)] = pr[r][1];
        }
    } else {               // plain: sPiv[i][kk]
        #pragma unroll
        for (int r = 0; r < 8; r++) {
            sPiv[(w * 8 + r) * 68 + l]      = pr[r][0];
            sPiv[(w * 8 + r) * 68 + l + 32] = pr[r][1];
        }
    }
    __syncthreads();

    // ---- 64x64x64 GEMM ----
    const float* AsT = (role == 0) ? sPiv : sOp;
    const float* Bs  = (role == 0) ? sOp  : sPiv;
    const int j0 = (tid & 15) * 4;
    const int i0 = (tid >> 4) * 4;
    float acc[4][4] = {};
    #pragma unroll 8
    for (int kk = 0; kk < NB; kk++) {
        const float4 a = *(const float4*)(AsT + kk * 68 + i0);
        const float4 v = *(const float4*)(Bs  + kk * 68 + j0);
        acc[0][0] += a.x * v.x; acc[0][1] += a.x * v.y; acc[0][2] += a.x * v.z; acc[0][3] += a.x * v.w;
        acc[1][0] += a.y * v.x; acc[1][1] += a.y * v.y; acc[1][2] += a.y * v.z; acc[1][3] += a.y * v.w;
        acc[2][0] += a.z * v.x; acc[2][1] += a.z * v.y; acc[2][2] += a.z * v.z; acc[2][3] += a.z * v.w;
        acc[3][0] += a.w * v.x; acc[3][1] += a.w * v.y; acc[3][2] += a.w * v.z; acc[3][3] += a.w * v.w;
    }

    float* Cg = (role == 0)
        ? g_M + base + (((size_t)k  * NB) << 10) + (size_t)jb * NB
        : g_M + base + (((size_t)ib * NB) << 10) + (size_t)k  * NB;
    const float sgn = (role == 0) ? 1.0f : -1.0f;
    #pragma unroll
    for (int r = 0; r < 4; r++) {
        float4 c;
        c.x = sgn * acc[r][0]; c.y = sgn * acc[r][1];
        c.z = sgn * acc[r][2]; c.w = sgn * acc[r][3];
        *(float4*)(Cg + ((size_t)(i0 + r) << 10) + j0) = c;
    }
}

// =====================================================================
// Trailing update: C(ib,jb) += L_new(ib,k) @ Rold(k,jb)  [Rold from g_S]
// CTA (0,0,b) also copies P^-1 from g_S slot k into g_M(k,k).
// =====================================================================
__global__ void __launch_bounds__(256) k_trail(int k) {
    __shared__ float AsT[NB * 68];
    __shared__ float Bs [NB * 68];
    const int b  = blockIdx.z;
    const int ib = blockIdx.y + ((int)blockIdx.y >= k);
    const int jb = blockIdx.x + ((int)blockIdx.x >= k);
    const size_t base = (size_t)b << 20;
    const int tid = threadIdx.x;

    const float* Ag = g_M + base + (((size_t)ib * NB) << 10) + (size_t)k * NB;   // new col panel L
    const float* Bg = g_S + ((size_t)b << 16) + (size_t)jb * NB;                 // stashed old row
    float*       Cg = g_M + base + (((size_t)ib * NB) << 10) + (size_t)jb * NB;

    #pragma unroll
    for (int f = tid; f < 1024; f += 256) {
        const int r = f >> 4, c4 = (f & 15) << 2;
        float4 av = *(const float4*)(Ag + ((size_t)r << 10) + c4);
        AsT[(c4 + 0) * 68 + r] = av.x;
        AsT[(c4 + 1) * 68 + r] = av.y;
        AsT[(c4 + 2) * 68 + r] = av.z;
        AsT[(c4 + 3) * 68 + r] = av.w;
        *(float4*)(Bs + r * 68 + c4) = *(const float4*)(Bg + (size_t)r * SS + c4);
    }
    __syncthreads();

    const int j0 = (tid & 15) * 4;
    const int i0 = (tid >> 4) * 4;
    float acc[4][4] = {};
    #pragma unroll 8
    for (int kk = 0; kk < NB; kk++) {
        const float4 a = *(const float4*)(AsT + kk * 68 + i0);
        const float4 v = *(const float4*)(Bs  + kk * 68 + j0);
        acc[0][0] += a.x * v.x; acc[0][1] += a.x * v.y; acc[0][2] += a.x * v.z; acc[0][3] += a.x * v.w;
        acc[1][0] += a.y * v.x; acc[1][1] += a.y * v.y; acc[1][2] += a.y * v.z; acc[1][3] += a.y * v.w;
        acc[2][0] += a.z * v.x; acc[2][1] += a.z * v.y; acc[2][2] += a.z * v.z; acc[2][3] += a.z * v.w;
        acc[3][0] += a.w * v.x; acc[3][1] += a.w * v.y; acc[3][2] += a.w * v.z; acc[3][3] += a.w * v.w;
    }
    #pragma unroll
    for (int r = 0; r < 4; r++) {
        float4 c = *(float4*)(Cg + ((size_t)(i0 + r) << 10) + j0);
        c.x += acc[r][0]; c.y += acc[r][1]; c.z += acc[r][2]; c.w += acc[r][3];
        *(float4*)(Cg + ((size_t)(i0 + r) << 10) + j0) = c;
    }

    // one CTA per batch installs P^-1 into the pivot block
    if (blockIdx.x == 0 && blockIdx.y == 0) {
        const float* Sg = g_S + ((size_t)b << 16) + (size_t)k * NB;
        float* Pg = g_M + base + (((size_t)k * NB) << 10) + (size_t)k * NB;
        #pragma unroll
        for (int f = tid; f < 1024; f += 256) {
            const int r = f >> 4, c4 = (f & 15) << 2;
            *(float4*)(Pg + ((size_t)r << 10) + c4) = *(const float4*)(Sg + (size_t)r * SS + c4);
        }
    }
}

// ---------------- tiled transpose: g_MT[b] = g_M[b]^T ----------------
__global__ void k_transpose() {
    __shared__ float tile[32][33];
    const int b = blockIdx.z;
    const int x0 = blockIdx.x * 32, y0 = blockIdx.y * 32;
    const size_t base = (size_t)b << 20;
    for (int r = threadIdx.y; r < 32; r += 8)
        tile[r][threadIdx.x] = g_M[base + ((size_t)(y0 + r) << 10) + x0 + threadIdx.x];
    __syncthreads();
    for (int r = threadIdx.y; r < 32; r += 8)
        g_MT[base + ((size_t)(x0 + r) << 10) + y0 + threadIdx.x] = tile[threadIdx.x][r];
}

// ---------------- assemble probs ----------------
__global__ void k_out(const float* __restrict__ s, float* __restrict__ out) {
    const size_t t = (size_t)blockIdx.x * 256 + threadIdx.x;   // exactly 16M threads
    const int q = (int)(t & 1023);
    const int p = (int)((t >> 10) & 1023);
    const int b = (int)(t >> 20);
    const float m = get_m();
    const unsigned int amax = (unsigned int)(g_maxkey & 0xffffffffu);
    float v = 0.0f;
    if (p >= 1) {
        const float* MT = g_MT + ((size_t)b << 20) + ((size_t)(p - 1) << 10);
        const float dg  = MT[p - 1];                     // Minv[p-1][p-1]
        const float sub = (q >= 1) ? MT[q - 1] : 0.0f;   // Minv[q-1][p-1]
        v = expf(s[t] - m) * (dg - sub);
    }
    if ((unsigned int)t == amax) v += 16.0f;             // grad through the global max
    out[t] = v;
}

extern "C" void kernel_launch(void* const* d_in, const int* in_sizes, int n_in,
                              void* d_out, int out_size) {
    (void)in_sizes; (void)n_in; (void)out_size;
    const float* s = (const float*)d_in[0];
    float* out = (float*)d_out;

    k_max<<<2048, 256>>>(s);
    k_rowsum<<<BB * SS, 256>>>(s);
    k_build<<<65536, 256>>>(s);

    for (int k = 0; k < NSTEP; k++) {
        k_panel<<<dim3(31, BB), 256>>>(k);
        k_trail<<<dim3(NSTEP - 1, NSTEP - 1, BB), 256>>>(k);
    }

    k_transpose<<<dim3(32, 32, BB), dim3(32, 8)>>>();
    k_out<<<65536, 256>>>(s, out);
}

// round 4
// speedup vs baseline: 1.5211x; 1.1001x over previous
#include <cuda_runtime.h>
#include <math.h>

#define BB 16
#define SS 1024
#define NB 64
#define NSTEP 16   // 1024/64

// ---- static device scratch (allocation-free) ----
static __device__ float g_M [(size_t)BB * SS * SS];   // 64 MB: padded minors -> inverses
static __device__ float g_MT[(size_t)BB * SS * SS];   // 64 MB: transposed inverses
static __device__ float g_S [(size_t)BB * NB * SS];   // 4 MB: stashed old row stripe
static __device__ float g_P [(size_t)BB * NB * NB];   // 256 KB: current pivot inverse P^-1
static __device__ double g_r[BB * SS];                // fp64 row sums
static __device__ unsigned long long g_maxkey;        // (sortable-key<<32)|argmax

__device__ __forceinline__ unsigned int enc_f(float v) {
    unsigned int u = __float_as_uint(v);
    return (u & 0x80000000u) ? ~u : (u | 0x80000000u);
}
__device__ __forceinline__ float dec_f(unsigned int k) {
    unsigned int u = (k & 0x80000000u) ? (k ^ 0x80000000u) : ~k;
    return __uint_as_float(u);
}
__device__ __forceinline__ float get_m() { return dec_f((unsigned int)(g_maxkey >> 32)); }

// ---- register Gauss-Jordan inversion of a 64x64 block ----
// pr[r][c] = M[w*8+r][l+32c]; 8 warps x 8 rows, 2 cols per lane.
// All 256 threads of the CTA must call this together.
__device__ __forceinline__ void gj64(float pr[8][2], float (*rowbuf)[64], int w, int l) {
    for (int pw = 0; pw < 8; pw++) {             // rolled: small I$ footprint
        #pragma unroll
        for (int rp = 0; rp < 8; rp++) {
            const int p = pw * 8 + rp;
            float* buf = rowbuf[rp & 1];
            if (w == pw) { buf[l] = pr[rp][0]; buf[l + 32] = pr[rp][1]; }
            __syncthreads();
            const float r0 = buf[l], r1 = buf[l + 32];
            const float pinv = 1.0f / buf[p];
            const bool hi = (p >= 32);
            const int pl = p & 31;
            #pragma unroll
            for (int r = 0; r < 8; r++) {
                const float src = hi ? pr[r][1] : pr[r][0];
                const float colv = __shfl_sync(0xffffffffu, src, pl);
                if (r == rp && w == pw) {
                    pr[r][0] = r0 * pinv;
                    pr[r][1] = r1 * pinv;
                    if (l == pl) { if (hi) pr[r][1] = pinv; else pr[r][0] = pinv; }
                } else {
                    const float sc = colv * pinv;
                    pr[r][0] -= sc * r0;
                    pr[r][1] -= sc * r1;
                    if (l == pl) { if (hi) pr[r][1] = -sc; else pr[r][0] = -sc; }
                }
            }
        }
    }
}

// ---------------- global max + argmax ----------------
__global__ void k_max(const float* __restrict__ s) {
    __shared__ unsigned long long sm[256];
    unsigned long long best = 0ULL;
    const size_t total = (size_t)BB * SS * SS;
    for (size_t i = (size_t)blockIdx.x * blockDim.x + threadIdx.x; i < total;
         i += (size_t)gridDim.x * blockDim.x) {
        unsigned long long c = ((unsigned long long)enc_f(s[i]) << 32) | (unsigned int)i;
        if (c > best) best = c;
    }
    sm[threadIdx.x] = best;
    __syncthreads();
    for (int o = 128; o > 0; o >>= 1) {
        if (threadIdx.x < o && sm[threadIdx.x + o] > sm[threadIdx.x]) sm[threadIdx.x] = sm[threadIdx.x + o];
        __syncthreads();
    }
    if (threadIdx.x == 0) atomicMax(&g_maxkey, sm[0]);
}

// ---------------- fp64 row sums of A = exp(s - m) ----------------
__global__ void k_rowsum(const float* __restrict__ s) {
    __shared__ double sd[256];
    const int row = blockIdx.x;
    const float m = get_m();
    const float* p = s + ((size_t)row << 10);
    double acc = 0.0;
    for (int j = threadIdx.x; j < SS; j += 256) acc += (double)expf(p[j] - m);
    sd[threadIdx.x] = acc;
    __syncthreads();
    for (int o = 128; o > 0; o >>= 1) {
        if (threadIdx.x < o) sd[threadIdx.x] += sd[threadIdx.x + o];
        __syncthreads();
    }
    if (threadIdx.x == 0) g_r[row] = sd[0];
}

// ---------------- build padded M (identity row/col at index 1023) ----------------
__global__ void k_build(const float* __restrict__ s) {
    const float m = get_m();
    const size_t t = (size_t)blockIdx.x * 256 + threadIdx.x;
    const int q = (int)(t & 1023);
    const int p = (int)((t >> 10) & 1023);
    const int b = (int)(t >> 20);
    float v;
    if (p < 1023 && q < 1023) {
        float a = expf(s[((size_t)b << 20) + ((size_t)(p + 1) << 10) + (q + 1)] - m);
        v = -a;
        if (p == q) v = (float)(g_r[b * SS + p + 1] - (double)a);
    } else {
        v = (p == q) ? 1.0f : 0.0f;
    }
    g_M[t] = v;
}

// ---------------- initial pivot inversion: g_P = inv(M(0,0)) ----------------
__global__ void __launch_bounds__(256) k_inv0() {
    __shared__ float rowbuf[2][64];
    const int b = blockIdx.x, tid = threadIdx.x;
    const int w = tid >> 5, l = tid & 31;
    float pr[8][2];
    const float* Pg = g_M + ((size_t)b << 20);   // block (0,0)
    #pragma unroll
    for (int r = 0; r < 8; r++) {
        pr[r][0] = Pg[((size_t)(w * 8 + r) << 10) + l];
        pr[r][1] = Pg[((size_t)(w * 8 + r) << 10) + l + 32];
    }
    gj64(pr, rowbuf, w, l);
    float* Pd = g_P + ((size_t)b << 12);
    #pragma unroll
    for (int r = 0; r < 8; r++) {
        Pd[(w * 8 + r) * NB + l]      = pr[r][0];
        Pd[(w * 8 + r) * NB + l + 32] = pr[r][1];
    }
}

// =====================================================================
// Panel kernel (no inversion): grid (30, BB)
//   x in [0,15) : row panel  C(k,jb) = P^-1 @ Aold(k,jb); stash Aold -> g_S
//   x in [15,30): col panel  C(ib,k) = -Aold(ib,k) @ P^-1
// P^-1 read from g_P.
// =====================================================================
__global__ void __launch_bounds__(256) k_panel(int k) {
    __shared__ float sOp [NB * 68];
    __shared__ float sPiv[NB * 68];
    const int b = blockIdx.y;
    const int x = blockIdx.x;
    const int tid = threadIdx.x;
    const size_t base = (size_t)b << 20;
    const int role = (x < 15) ? 0 : 1;
    const float* Pd = g_P + ((size_t)b << 12);

    int ib = k, jb = k;
    if (role == 0) {
        jb = x + (x >= k);
        const float* Bg = g_M + base + (((size_t)k * NB) << 10) + (size_t)jb * NB;
        float* Sg = g_S + ((size_t)b << 16) + (size_t)jb * NB;
        #pragma unroll
        for (int f = tid; f < 1024; f += 256) {
            const int r = f >> 4, c4 = (f & 15) << 2;
            float4 v = *(const float4*)(Bg + ((size_t)r << 10) + c4);
            *(float4*)(sOp + r * 68 + c4) = v;                 // Bs plain
            *(float4*)(Sg + (size_t)r * SS + c4) = v;          // stash old row tile
            // P^-1 transposed: sPiv[kk][i] = Pinv[i][kk]
            float4 pv = *(const float4*)(Pd + r * NB + c4);
            sPiv[(c4 + 0) * 68 + r] = pv.x;
            sPiv[(c4 + 1) * 68 + r] = pv.y;
            sPiv[(c4 + 2) * 68 + r] = pv.z;
            sPiv[(c4 + 3) * 68 + r] = pv.w;
        }
    } else {
        ib = (x - 15) + ((x - 15) >= k);
        const float* Ag = g_M + base + (((size_t)ib * NB) << 10) + (size_t)k * NB;
        #pragma unroll
        for (int f = tid; f < 1024; f += 256) {
            const int r = f >> 4, c4 = (f & 15) << 2;
            float4 v = *(const float4*)(Ag + ((size_t)r << 10) + c4);
            sOp[(c4 + 0) * 68 + r] = v.x;                      // AsT[k][i]
            sOp[(c4 + 1) * 68 + r] = v.y;
            sOp[(c4 + 2) * 68 + r] = v.z;
            sOp[(c4 + 3) * 68 + r] = v.w;
            *(float4*)(sPiv + r * 68 + c4) = *(const float4*)(Pd + r * NB + c4);  // plain
        }
    }
    __syncthreads();

    const float* AsT = (role == 0) ? sPiv : sOp;
    const float* Bs  = (role == 0) ? sOp  : sPiv;
    const int j0 = (tid & 15) * 4;
    const int i0 = (tid >> 4) * 4;
    float acc[4][4] = {};
    #pragma unroll 8
    for (int kk = 0; kk < NB; kk++) {
        const float4 a = *(const float4*)(AsT + kk * 68 + i0);
        const float4 v = *(const float4*)(Bs  + kk * 68 + j0);
        acc[0][0] += a.x * v.x; acc[0][1] += a.x * v.y; acc[0][2] += a.x * v.z; acc[0][3] += a.x * v.w;
        acc[1][0] += a.y * v.x; acc[1][1] += a.y * v.y; acc[1][2] += a.y * v.z; acc[1][3] += a.y * v.w;
        acc[2][0] += a.z * v.x; acc[2][1] += a.z * v.y; acc[2][2] += a.z * v.z; acc[2][3] += a.z * v.w;
        acc[3][0] += a.w * v.x; acc[3][1] += a.w * v.y; acc[3][2] += a.w * v.z; acc[3][3] += a.w * v.w;
    }

    float* Cg = (role == 0)
        ? g_M + base + (((size_t)k  * NB) << 10) + (size_t)jb * NB
        : g_M + base + (((size_t)ib * NB) << 10) + (size_t)k  * NB;
    const float sgn = (role == 0) ? 1.0f : -1.0f;
    #pragma unroll
    for (int r = 0; r < 4; r++) {
        float4 c;
        c.x = sgn * acc[r][0]; c.y = sgn * acc[r][1];
        c.z = sgn * acc[r][2]; c.w = sgn * acc[r][3];
        *(float4*)(Cg + ((size_t)(i0 + r) << 10) + j0) = c;
    }
}

// =====================================================================
// Trailing update: C(ib,jb) += L_new(ib,k) @ Rold(k,jb)  [Rold from g_S]
// Block mapping puts tile (k+1,k+1) at blockIdx (0,0); that CTA additionally:
//   - installs P^-1(k) from g_P into g_M(k,k)
//   - inverts its freshly updated tile (the next pivot) -> g_P   (skip k=15)
// =====================================================================
__global__ void __launch_bounds__(256) k_trail(int k) {
    __shared__ float AsT[NB * 68];
    __shared__ float Bs [NB * 68];
    __shared__ float rowbuf[2][64];
    const int b  = blockIdx.z;
    const int ib = (k + 1 + blockIdx.y) & 15;   // enumerates all blocks != k
    const int jb = (k + 1 + blockIdx.x) & 15;
    const size_t base = (size_t)b << 20;
    const int tid = threadIdx.x;
    const bool special = (blockIdx.x == 0 && blockIdx.y == 0);

    if (special) {   // install P^-1(k) into g_M(k,k); nobody else touches it this step
        const float* Pd = g_P + ((size_t)b << 12);
        float* Pg = g_M + base + (((size_t)k * NB) << 10) + (size_t)k * NB;
        #pragma unroll
        for (int f = tid; f < 1024; f += 256) {
            const int r = f >> 4, c4 = (f & 15) << 2;
            *(float4*)(Pg + ((size_t)r << 10) + c4) = *(const float4*)(Pd + r * NB + c4);
        }
    }

    const float* Ag = g_M + base + (((size_t)ib * NB) << 10) + (size_t)k * NB;   // new col panel L
    const float* Bg = g_S + ((size_t)b << 16) + (size_t)jb * NB;                 // stashed old row
    float*       Cg = g_M + base + (((size_t)ib * NB) << 10) + (size_t)jb * NB;

    #pragma unroll
    for (int f = tid; f < 1024; f += 256) {
        const int r = f >> 4, c4 = (f & 15) << 2;
        float4 av = *(const float4*)(Ag + ((size_t)r << 10) + c4);
        AsT[(c4 + 0) * 68 + r] = av.x;
        AsT[(c4 + 1) * 68 + r] = av.y;
        AsT[(c4 + 2) * 68 + r] = av.z;
        AsT[(c4 + 3) * 68 + r] = av.w;
        *(float4*)(Bs + r * 68 + c4) = *(const float4*)(Bg + (size_t)r * SS + c4);
    }
    __syncthreads();

    const int j0 = (tid & 15) * 4;
    const int i0 = (tid >> 4) * 4;
    float acc[4][4] = {};
    #pragma unroll 8
    for (int kk = 0; kk < NB; kk++) {
        const float4 a = *(const float4*)(AsT + kk * 68 + i0);
        const float4 v = *(const float4*)(Bs  + kk * 68 + j0);
        acc[0][0] += a.x * v.x; acc[0][1] += a.x * v.y; acc[0][2] += a.x * v.z; acc[0][3] += a.x * v.w;
        acc[1][0] += a.y * v.x; acc[1][1] += a.y * v.y; acc[1][2] += a.y * v.z; acc[1][3] += a.y * v.w;
        acc[2][0] += a.z * v.x; acc[2][1] += a.z * v.y; acc[2][2] += a.z * v.z; acc[2][3] += a.z * v.w;
        acc[3][0] += a.w * v.x; acc[3][1] += a.w * v.y; acc[3][2] += a.w * v.z; acc[3][3] += a.w * v.w;
    }
    #pragma unroll
    for (int r = 0; r < 4; r++) {
        float4 c = *(float4*)(Cg + ((size_t)(i0 + r) << 10) + j0);
        c.x += acc[r][0]; c.y += acc[r][1]; c.z += acc[r][2]; c.w += acc[r][3];
        acc[r][0] = c.x; acc[r][1] = c.y; acc[r][2] = c.z; acc[r][3] = c.w;
        *(float4*)(Cg + ((size_t)(i0 + r) << 10) + j0) = c;
    }

    // ---- fused next-pivot inversion (tile (k+1,k+1), complete after this update) ----
    if (special && k < NSTEP - 1) {
        __syncthreads();   // AsT reads done everywhere; safe to repurpose as staging
        #pragma unroll
        for (int r = 0; r < 4; r++) {
            AsT[(i0 + r) * 68 + j0 + 0] = acc[r][0];
            AsT[(i0 + r) * 68 + j0 + 1] = acc[r][1];
            AsT[(i0 + r) * 68 + j0 + 2] = acc[r][2];
            AsT[(i0 + r) * 68 + j0 + 3] = acc[r][3];
        }
        __syncthreads();
        const int w = tid >> 5, l = tid & 31;
        float pr[8][2];
        #pragma unroll
        for (int r = 0; r < 8; r++) {
            pr[r][0] = AsT[(w * 8 + r) * 68 + l];
            pr[r][1] = AsT[(w * 8 + r) * 68 + l + 32];
        }
        gj64(pr, rowbuf, w, l);
        float* Pd = g_P + ((size_t)b << 12);
        #pragma unroll
        for (int r = 0; r < 8; r++) {
            Pd[(w * 8 + r) * NB + l]      = pr[r][0];
            Pd[(w * 8 + r) * NB + l + 32] = pr[r][1];
        }
    }
}

// ---------------- tiled transpose: g_MT[b] = g_M[b]^T ----------------
__global__ void k_transpose() {
    __shared__ float tile[32][33];
    const int b = blockIdx.z;
    const int x0 = blockIdx.x * 32, y0 = blockIdx.y * 32;
    const size_t base = (size_t)b << 20;
    for (int r = threadIdx.y; r < 32; r += 8)
        tile[r][threadIdx.x] = g_M[base + ((size_t)(y0 + r) << 10) + x0 + threadIdx.x];
    __syncthreads();
    for (int r = threadIdx.y; r < 32; r += 8)
        g_MT[base + ((size_t)(x0 + r) << 10) + y0 + threadIdx.x] = tile[threadIdx.x][r];
}

// ---------------- assemble probs ----------------
__global__ void k_out(const float* __restrict__ s, float* __restrict__ out) {
    const size_t t = (size_t)blockIdx.x * 256 + threadIdx.x;
    const int q = (int)(t & 1023);
    const int p = (int)((t >> 10) & 1023);
    const int b = (int)(t >> 20);
    const float m = get_m();
    const unsigned int amax = (unsigned int)(g_maxkey & 0xffffffffu);
    float v = 0.0f;
    if (p >= 1) {
        const float* MT = g_MT + ((size_t)b << 20) + ((size_t)(p - 1) << 10);
        const float dg  = MT[p - 1];                     // Minv[p-1][p-1]
        const float sub = (q >= 1) ? MT[q - 1] : 0.0f;   // Minv[q-1][p-1]
        v = expf(s[t] - m) * (dg - sub);
    }
    if ((unsigned int)t == amax) v += 16.0f;             // grad through the global max
    out[t] = v;
}

extern "C" void kernel_launch(void* const* d_in, const int* in_sizes, int n_in,
                              void* d_out, int out_size) {
    (void)in_sizes; (void)n_in; (void)out_size;
    const float* s = (const float*)d_in[0];
    float* out = (float*)d_out;

    k_max<<<2048, 256>>>(s);
    k_rowsum<<<BB * SS, 256>>>(s);
    k_build<<<65536, 256>>>(s);
    k_inv0<<<BB, 256>>>();

    for (int k = 0; k < NSTEP; k++) {
        k_panel<<<dim3(30, BB), 256>>>(k);
        k_trail<<<dim3(NSTEP - 1, NSTEP - 1, BB), 256>>>(k);
    }

    k_transpose<<<dim3(32, 32, BB), dim3(32, 8)>>>();
    k_out<<<65536, 256>>>(s, out);
}